// round 3
// baseline (speedup 1.0000x reference)
#include <cuda_runtime.h>
#include <math.h>
#include <stdint.h>

#define BB 4
#define NLN 2048
#define CC 128
#define HH 128
#define WW 128
#define NPTS0 32
#define NPTS1 8
#define NLINES (BB*NLN)   // 8192
#define PP 64

// -------- scratch (__device__ globals: allocation-free) --------
__device__ float g_fmt[(size_t)BB*HH*WW*CC];   // (B,H,W,C) fp32, 33.5MB
__device__ float g_x[(size_t)NLINES*CC*NPTS1]; // (line, C, 8) fp32, 33.5MB

// ================= kernel 1: transpose (B,C,H,W) -> (B,H,W,C) =================
__global__ void k_transpose(const float* __restrict__ fm) {
    __shared__ float tile[32][33];
    int bh = blockIdx.z;            // b*128 + h
    int b = bh >> 7, h = bh & 127;
    int c0 = blockIdx.y * 32, w0 = blockIdx.x * 32;
    int tx = threadIdx.x, ty = threadIdx.y;
    #pragma unroll
    for (int i = 0; i < 32; i += 8) {
        int c = c0 + ty + i;
        tile[ty + i][tx] = fm[(((size_t)b*CC + c)*HH + h)*WW + w0 + tx];
    }
    __syncthreads();
    #pragma unroll
    for (int i = 0; i < 32; i += 8) {
        int w = w0 + ty + i;
        g_fmt[(((size_t)b*HH + h)*WW + w)*CC + c0 + tx] = tile[tx][ty + i];
    }
}

// ================= kernel 2: LOI gather + bilinear + maxpool(4) =================
// one block per line, 128 threads = channels; taps are 512B coalesced reads from g_fmt
__global__ void k_gather(const float* __restrict__ lines) {
    int line = blockIdx.x;            // 0..8191
    int b = line >> 11;               // / NLN
    int c = threadIdx.x;              // 0..127
    const float* lp = lines + (size_t)line * 4;
    float e0x = lp[0], e0y = lp[1], e1x = lp[2], e1y = lp[3];
    const float* fmt = g_fmt + (size_t)b * HH * WW * CC;

    float mx[NPTS1];
    #pragma unroll
    for (int g = 0; g < NPTS1; g++) {
        float m = -3.4e38f;
        #pragma unroll
        for (int j = 0; j < 4; j++) {
            int t = g * 4 + j;
            float lam = (float)t * (1.0f / 31.0f);
            float px = e0x * lam + e1x * (1.0f - lam) - 0.5f;
            float py = e0y * lam + e1y * (1.0f - lam) - 0.5f;
            float fx0 = fminf(fmaxf(floorf(px), 0.0f), 127.0f);
            float fy0 = fminf(fmaxf(floorf(py), 0.0f), 127.0f);
            float fx1 = fminf(fx0 + 1.0f, 127.0f);
            float fy1 = fminf(fy0 + 1.0f, 127.0f);
            int x0 = (int)fx0, y0 = (int)fy0, x1 = (int)fx1, y1 = (int)fy1;
            // NOTE: weight assignment replicates the reference exactly
            // (taps (y1,x0)/(y0,x1) carry the "swapped" weights)
            float wa = (fx1 - px) * (fy1 - py);   // tap (y0,x0)
            float wb = (px - fx0) * (fy1 - py);   // tap (y1,x0)
            float wc = (fx1 - px) * (py - fy0);   // tap (y0,x1)
            float wd = (px - fx0) * (py - fy0);   // tap (y1,x1)
            float v00 = fmt[((size_t)(y0 * WW + x0)) * CC + c];
            float v10 = fmt[((size_t)(y1 * WW + x0)) * CC + c];
            float v01 = fmt[((size_t)(y0 * WW + x1)) * CC + c];
            float v11 = fmt[((size_t)(y1 * WW + x1)) * CC + c];
            float s = wa * v00 + wb * v10 + wc * v01 + wd * v11;
            m = fmaxf(m, s);
        }
        mx[g] = m;
    }
    float* xo = g_x + ((size_t)line * CC + c) * NPTS1;
    #pragma unroll
    for (int g = 0; g < NPTS1; g++) xo[g] = mx[g];
}

// ================= kernel 3: fused conv stack + residual + FC + softmax ========
// 8 lines per block (M = 64 rows of (line,t)), 256 threads, three smem GEMMs.
// dynamic smem layout (floats):
//   sW1 [128k][64n]   8192
//   sW2 [192k][64n]  12288
//   sW3 [ 64k][128n]  8192
//   sX  [8ln][128c*8t] 8192   (raw x, residual base, later x+y)
//   sA  [192k][64m]  12288   (im2col / activation staging, reused per GEMM)
//   sPar 768
#define SM_FLOATS (8192 + 12288 + 8192 + 8192 + 12288 + 768)

__global__ void __launch_bounds__(256, 1)
k_conv(const float* __restrict__ lines,
       const float* __restrict__ bn1_g, const float* __restrict__ bn1_b,
       const float* __restrict__ conv1_w, const float* __restrict__ conv1_b,
       const float* __restrict__ bn2_g, const float* __restrict__ bn2_b,
       const float* __restrict__ conv2_w, const float* __restrict__ conv2_b,
       const float* __restrict__ bn3_g, const float* __restrict__ bn3_b,
       const float* __restrict__ conv3_w, const float* __restrict__ conv3_b,
       const float* __restrict__ fc2_w, const float* __restrict__ fc2_b,
       float* __restrict__ out)
{
    extern __shared__ float smem[];
    float* sW1 = smem;                  // [k*64+n]
    float* sW2 = sW1 + 8192;            // [k*64+n], k<192
    float* sW3 = sW2 + 12288;           // [k*128+n], k<64
    float* sX  = sW3 + 8192;            // [ln*1024 + c*8 + t]
    float* sA  = sX  + 8192;            // [k*64 + m]
    float* sPar = sA + 12288;
    float* s1  = sPar;        float* b1  = sPar + 128;
    float* c1b = sPar + 256;  float* s2  = sPar + 320;
    float* b2  = sPar + 384;  float* c2b = sPar + 448;
    float* s3  = sPar + 512;  float* b3  = sPar + 576;
    float* c3b = sPar + 640;

    int tid = threadIdx.x;
    const float rs = rsqrtf(1.0f + 1e-5f);

    // ---- stage params + weights + x ----
    for (int i = tid; i < 128; i += 256) {
        s1[i] = bn1_g[i] * rs; b1[i] = bn1_b[i]; c3b[i] = conv3_b[i];
    }
    for (int i = tid; i < 64; i += 256) {
        c1b[i] = conv1_b[i];
        s2[i] = bn2_g[i] * rs; b2[i] = bn2_b[i];
        c2b[i] = conv2_b[i];
        s3[i] = bn3_g[i] * rs; b3[i] = bn3_b[i];
    }
    for (int i = tid; i < 8192; i += 256) {         // W1 (64p,128c) -> [c][p]
        int p = i >> 7, c = i & 127;
        sW1[c * 64 + p] = conv1_w[i];
    }
    for (int i = tid; i < 12288; i += 256) {        // W2 (64p,64q,3k) -> [kk*64+q][p]
        int p = i / 192, r = i - p * 192, q = r / 3, kk = r - q * 3;
        sW2[(kk * 64 + q) * 64 + p] = conv2_w[i];
    }
    for (int i = tid; i < 8192; i += 256) {         // W3 (128c,64p) -> [p][c]
        int c = i >> 6, p = i & 63;
        sW3[p * 128 + c] = conv3_w[i];
    }
    {
        const float4* src = (const float4*)(g_x + (size_t)blockIdx.x * 8 * 1024);
        float4* dst = (float4*)sX;
        for (int i = tid; i < 2048; i += 256) dst[i] = src[i];
    }
    __syncthreads();

    // ---- y = relu(bn1(x)) into sA[c][m] ----
    for (int i = tid; i < 8192; i += 256) {
        int c = i >> 6, m = i & 63;
        int ln = m >> 3, t = m & 7;
        sA[i] = fmaxf(s1[c] * sX[ln * 1024 + c * 8 + t] + b1[c], 0.0f);
    }
    __syncthreads();

    // ---- GEMM1: out1[m][p] = sum_c W1[p][c] * y[c][m], K=128, 4x4 tiles ----
    int tn = tid & 15, tm = tid >> 4;
    int n0 = tn * 4, m0 = tm * 4;
    float acc[4][4] = {};
    #pragma unroll 4
    for (int k = 0; k < 128; k++) {
        float4 a = *(const float4*)&sW1[k * 64 + n0];
        float4 bv = *(const float4*)&sA[k * 64 + m0];
        acc[0][0] += bv.x * a.x; acc[0][1] += bv.x * a.y; acc[0][2] += bv.x * a.z; acc[0][3] += bv.x * a.w;
        acc[1][0] += bv.y * a.x; acc[1][1] += bv.y * a.y; acc[1][2] += bv.y * a.z; acc[1][3] += bv.y * a.w;
        acc[2][0] += bv.z * a.x; acc[2][1] += bv.z * a.y; acc[2][2] += bv.z * a.z; acc[2][3] += bv.z * a.w;
        acc[3][0] += bv.w * a.x; acc[3][1] += bv.w * a.y; acc[3][2] += bv.w * a.z; acc[3][3] += bv.w * a.w;
    }
    __syncthreads();

    // ---- zero pad slots, then im2col scatter of relu(bn2(out1)) into sA[kk*64+q][m] ----
    for (int i = tid; i < 1024; i += 256) {
        int q = i & 63, r = i >> 6, ln = r & 7, half = r >> 3;
        if (half == 0) sA[q * 64 + ln * 8 + 0] = 0.0f;          // kk=0, t2=0
        else           sA[(128 + q) * 64 + ln * 8 + 7] = 0.0f;  // kk=2, t2=7
    }
    #pragma unroll
    for (int mi = 0; mi < 4; mi++) {
        int m = m0 + mi, ln = m >> 3, t = m & 7;
        #pragma unroll
        for (int ni = 0; ni < 4; ni++) {
            int q = n0 + ni;
            float z = fmaxf(s2[q] * (acc[mi][ni] + c1b[q]) + b2[q], 0.0f);
            #pragma unroll
            for (int kk = 0; kk < 3; kk++) {
                int t2 = t + 1 - kk;
                if (t2 >= 0 && t2 < 8) sA[(kk * 64 + q) * 64 + ln * 8 + t2] = z;
            }
        }
    }
    __syncthreads();

    // ---- GEMM2: K=192, conv2 ----
    float acc2[4][4] = {};
    #pragma unroll 4
    for (int k = 0; k < 192; k++) {
        float4 a = *(const float4*)&sW2[k * 64 + n0];
        float4 bv = *(const float4*)&sA[k * 64 + m0];
        acc2[0][0] += bv.x * a.x; acc2[0][1] += bv.x * a.y; acc2[0][2] += bv.x * a.z; acc2[0][3] += bv.x * a.w;
        acc2[1][0] += bv.y * a.x; acc2[1][1] += bv.y * a.y; acc2[1][2] += bv.y * a.z; acc2[1][3] += bv.y * a.w;
        acc2[2][0] += bv.z * a.x; acc2[2][1] += bv.z * a.y; acc2[2][2] += bv.z * a.z; acc2[2][3] += bv.z * a.w;
        acc2[3][0] += bv.w * a.x; acc2[3][1] += bv.w * a.y; acc2[3][2] += bv.w * a.z; acc2[3][3] += bv.w * a.w;
    }
    __syncthreads();
    #pragma unroll
    for (int mi = 0; mi < 4; mi++) {
        #pragma unroll
        for (int ni = 0; ni < 4; ni++) {
            int q = n0 + ni;
            float z = fmaxf(s3[q] * (acc2[mi][ni] + c2b[q]) + b3[q], 0.0f);
            sA[q * 64 + m0 + mi] = z;       // rows 0..63 = conv3 input
        }
    }
    __syncthreads();

    // ---- GEMM3: out3[m][c] = sum_p W3[c][p]*z[p][m], K=64, N=128, 4x8 tiles ----
    int tn3 = tid & 15, tm3 = tid >> 4;
    int n03 = tn3 * 8, m03 = tm3 * 4;
    float acc3[4][8] = {};
    #pragma unroll 4
    for (int k = 0; k < 64; k++) {
        float4 a0 = *(const float4*)&sW3[k * 128 + n03];
        float4 a1 = *(const float4*)&sW3[k * 128 + n03 + 4];
        float4 bv = *(const float4*)&sA[k * 64 + m03];
        float bs[4] = { bv.x, bv.y, bv.z, bv.w };
        #pragma unroll
        for (int mi = 0; mi < 4; mi++) {
            acc3[mi][0] += bs[mi] * a0.x; acc3[mi][1] += bs[mi] * a0.y;
            acc3[mi][2] += bs[mi] * a0.z; acc3[mi][3] += bs[mi] * a0.w;
            acc3[mi][4] += bs[mi] * a1.x; acc3[mi][5] += bs[mi] * a1.y;
            acc3[mi][6] += bs[mi] * a1.z; acc3[mi][7] += bs[mi] * a1.w;
        }
    }
    // residual: x += y3 (each element owned by exactly one thread)
    #pragma unroll
    for (int mi = 0; mi < 4; mi++) {
        int m = m03 + mi, ln = m >> 3, t = m & 7;
        #pragma unroll
        for (int ni = 0; ni < 8; ni++) {
            int c = n03 + ni;
            sX[ln * 1024 + c * 8 + t] += acc3[mi][ni] + c3b[c];
        }
    }
    __syncthreads();

    // ---- FC2 + softmax: one warp per line ----
    int ln = tid >> 5, lane = tid & 31;
    int gline = blockIdx.x * 8 + ln;
    const float* xf = sX + ln * 1024;
    float a0 = 0.f, a1 = 0.f, a2 = 0.f, a3 = 0.f;
    #pragma unroll 8
    for (int j = 0; j < 32; j++) {
        int k = j * 32 + lane;
        float v = fmaxf(xf[k], 0.0f);
        a0 += v * __ldg(&fc2_w[k]);
        a1 += v * __ldg(&fc2_w[1029 + k]);
        a2 += v * __ldg(&fc2_w[2058 + k]);
        a3 += v * __ldg(&fc2_w[3087 + k]);
    }
    if (lane < 5) {
        const float* lp = lines + (size_t)gline * 4;
        float e0x = lp[0], e0y = lp[1], e1x = lp[2], e1y = lp[3];
        float f;
        if (lane == 0)      f = e0x * (1.0f / 128.0f);
        else if (lane == 1) f = e0y * (1.0f / 128.0f);
        else if (lane == 2) f = e1x * (1.0f / 128.0f);
        else if (lane == 3) f = e1y * (1.0f / 128.0f);
        else {
            float dx = e0x - e1x, dy = e0y - e1y;
            f = fmaxf(sqrtf(dx * dx + dy * dy), 1e-6f);
        }
        f = fmaxf(f, 0.0f);
        int k = 1024 + lane;
        a0 += f * __ldg(&fc2_w[k]);
        a1 += f * __ldg(&fc2_w[1029 + k]);
        a2 += f * __ldg(&fc2_w[2058 + k]);
        a3 += f * __ldg(&fc2_w[3087 + k]);
    }
    #pragma unroll
    for (int off = 16; off; off >>= 1) {
        a0 += __shfl_xor_sync(0xffffffffu, a0, off);
        a1 += __shfl_xor_sync(0xffffffffu, a1, off);
        a2 += __shfl_xor_sync(0xffffffffu, a2, off);
        a3 += __shfl_xor_sync(0xffffffffu, a3, off);
    }
    if (lane == 0) {
        float l0 = a0 + fc2_b[0], l1 = a1 + fc2_b[1];
        float l2 = a2 + fc2_b[2], l3 = a3 + fc2_b[3];
        float mx = fmaxf(fmaxf(l0, l1), fmaxf(l2, l3));
        float e0 = expf(l0 - mx), e1 = expf(l1 - mx);
        float e2 = expf(l2 - mx), e3 = expf(l3 - mx);
        float inv = 1.0f / (e0 + e1 + e2 + e3);
        out[(size_t)gline * 4 + 0] = l0;
        out[(size_t)gline * 4 + 1] = l1;
        out[(size_t)gline * 4 + 2] = l2;
        out[(size_t)gline * 4 + 3] = l3;
        float* pr = out + (size_t)NLINES * 4;
        pr[(size_t)gline * 4 + 0] = e0 * inv;
        pr[(size_t)gline * 4 + 1] = e1 * inv;
        pr[(size_t)gline * 4 + 2] = e2 * inv;
        pr[(size_t)gline * 4 + 3] = e3 * inv;
    }
}

// ================= launcher =================
extern "C" void kernel_launch(void* const* d_in, const int* in_sizes, int n_in,
                              void* d_out, int out_size) {
    const float* fm      = (const float*)d_in[0];
    const float* lines   = (const float*)d_in[1];
    const float* bn1_g   = (const float*)d_in[2];
    const float* bn1_b   = (const float*)d_in[3];
    const float* conv1_w = (const float*)d_in[4];
    const float* conv1_b = (const float*)d_in[5];
    const float* bn2_g   = (const float*)d_in[6];
    const float* bn2_b   = (const float*)d_in[7];
    const float* conv2_w = (const float*)d_in[8];
    const float* conv2_b = (const float*)d_in[9];
    const float* bn3_g   = (const float*)d_in[10];
    const float* bn3_b   = (const float*)d_in[11];
    const float* conv3_w = (const float*)d_in[12];
    const float* conv3_b = (const float*)d_in[13];
    const float* fc2_w   = (const float*)d_in[14];
    const float* fc2_b   = (const float*)d_in[15];
    float* out = (float*)d_out;

    static int smem_set = 0;
    if (!smem_set) {
        cudaFuncSetAttribute(k_conv, cudaFuncAttributeMaxDynamicSharedMemorySize,
                             SM_FLOATS * sizeof(float));
        smem_set = 1;
    }

    k_transpose<<<dim3(WW / 32, CC / 32, BB * HH), dim3(32, 8)>>>(fm);
    k_gather<<<NLINES, 128>>>(lines);
    k_conv<<<NLINES / 8, 256, SM_FLOATS * sizeof(float)>>>(
        lines, bn1_g, bn1_b, conv1_w, conv1_b, bn2_g, bn2_b,
        conv2_w, conv2_b, bn3_g, bn3_b, conv3_w, conv3_b,
        fc2_w, fc2_b, out);
}

// round 4
// speedup vs baseline: 2.8905x; 2.8905x over previous
#include <cuda_runtime.h>
#include <cuda_fp16.h>
#include <math.h>
#include <stdint.h>

#define BB 4
#define NLN 2048
#define CC 128
#define HH 128
#define WW 128
#define NPTS0 32
#define NPTS1 8
#define NLINES (BB*NLN)   // 8192
#define PP 64

// -------- scratch (__device__ globals: allocation-free) --------
__device__ float g_fmt[(size_t)BB*HH*WW*CC];   // (B,H,W,C) fp32
__device__ float g_x[(size_t)NLINES*NPTS1*CC]; // (line, t, C) fp32  <-- t-major now

// ================= kernel 1: transpose (B,C,H,W) -> (B,H,W,C) =================
__global__ void k_transpose(const float* __restrict__ fm) {
    __shared__ float tile[32][33];
    int bh = blockIdx.z;
    int b = bh >> 7, h = bh & 127;
    int c0 = blockIdx.y * 32, w0 = blockIdx.x * 32;
    int tx = threadIdx.x, ty = threadIdx.y;
    #pragma unroll
    for (int i = 0; i < 32; i += 8) {
        int c = c0 + ty + i;
        tile[ty + i][tx] = fm[(((size_t)b*CC + c)*HH + h)*WW + w0 + tx];
    }
    __syncthreads();
    #pragma unroll
    for (int i = 0; i < 32; i += 8) {
        int w = w0 + ty + i;
        g_fmt[(((size_t)b*HH + h)*WW + w)*CC + c0 + tx] = tile[tx][ty + i];
    }
}

// ================= kernel 2: LOI gather (float4) + bilinear + maxpool(4) =====
// one block per line; warp w handles points [8w,8w+8) = pool groups {2w,2w+1};
// lane handles channels [4l,4l+4) via float4. Taps are 512B coalesced LDG.128.
__device__ __forceinline__ float4 max4(float4 a, float4 b) {
    float4 r; r.x = fmaxf(a.x,b.x); r.y = fmaxf(a.y,b.y);
    r.z = fmaxf(a.z,b.z); r.w = fmaxf(a.w,b.w); return r;
}
__global__ void k_gather(const float* __restrict__ lines) {
    int line = blockIdx.x;
    int b = line >> 11;
    int w = threadIdx.x >> 5, l = threadIdx.x & 31;
    const float* lp = lines + (size_t)line * 4;
    float e0x = lp[0], e0y = lp[1], e1x = lp[2], e1y = lp[3];
    const float4* fmt = (const float4*)(g_fmt + (size_t)b * HH * WW * CC);

    float4 mx0, mx1;
    #pragma unroll
    for (int j = 0; j < 8; j++) {
        int t = w * 8 + j;
        float lam = (float)t * (1.0f / 31.0f);
        float px = e0x * lam + e1x * (1.0f - lam) - 0.5f;
        float py = e0y * lam + e1y * (1.0f - lam) - 0.5f;
        float fx0 = fminf(fmaxf(floorf(px), 0.0f), 127.0f);
        float fy0 = fminf(fmaxf(floorf(py), 0.0f), 127.0f);
        float fx1 = fminf(fx0 + 1.0f, 127.0f);
        float fy1 = fminf(fy0 + 1.0f, 127.0f);
        int x0 = (int)fx0, y0 = (int)fy0, x1 = (int)fx1, y1 = (int)fy1;
        float wa = (fx1 - px) * (fy1 - py);
        float wb = (px - fx0) * (fy1 - py);
        float wc = (fx1 - px) * (py - fy0);
        float wd = (px - fx0) * (py - fy0);
        float4 v00 = fmt[(size_t)(y0 * WW + x0) * 32 + l];
        float4 v10 = fmt[(size_t)(y1 * WW + x0) * 32 + l];
        float4 v01 = fmt[(size_t)(y0 * WW + x1) * 32 + l];
        float4 v11 = fmt[(size_t)(y1 * WW + x1) * 32 + l];
        float4 s;
        s.x = wa*v00.x + wb*v10.x + wc*v01.x + wd*v11.x;
        s.y = wa*v00.y + wb*v10.y + wc*v01.y + wd*v11.y;
        s.z = wa*v00.z + wb*v10.z + wc*v01.z + wd*v11.z;
        s.w = wa*v00.w + wb*v10.w + wc*v01.w + wd*v11.w;
        if (j == 0) mx0 = s;
        else if (j < 4) mx0 = max4(mx0, s);
        else if (j == 4) mx1 = s;
        else mx1 = max4(mx1, s);
    }
    float4* xo = (float4*)g_x;
    xo[((size_t)line * 8 + w * 2 + 0) * 32 + l] = mx0;
    xo[((size_t)line * 8 + w * 2 + 1) * 32 + l] = mx1;
}

// ================= kernel 3: HMMA conv stack + residual + FC + softmax ========
// 16 lines/block (M=128 rows, m = ln*8+t), 256 threads = 8 warps.
// Warp wid owns m-stripe [16*wid, 16*wid+16) => lines {2wid, 2wid+1}.
// GEMMs via mma.sync.m16n8k16 f16->f32. smem strides padded for conflict-free frags.
#define AS   200   // hA row stride (halves): 100 words, !=0 mod 32
#define W1S  136   // 68 words
#define W2S  200
#define W3S  72    // 36 words
#define SXS  132   // sX row stride (floats)

// byte offsets in dynamic smem
#define OFF_W1   0
#define OFF_W2   (OFF_W1 + 64*W1S*2)          // 17408
#define OFF_W3   (OFF_W2 + 64*W2S*2)          // +25600
#define OFF_A    (OFF_W3 + 128*W3S*2)         // +18432
#define OFF_SX   (OFF_A  + 128*AS*2)          // +51200
#define OFF_FC   (OFF_SX + 128*SXS*4)         // +67584
#define OFF_PAR  (OFF_FC + 4120*4)            // +16480
#define SMEM_BYTES (OFF_PAR + 768*4)          // +3072  => 199776

__device__ __forceinline__ void mma16816(float* c, uint32_t a0, uint32_t a1,
                                         uint32_t a2, uint32_t a3,
                                         uint32_t b0, uint32_t b1) {
    asm volatile(
        "mma.sync.aligned.m16n8k16.row.col.f32.f16.f16.f32 "
        "{%0,%1,%2,%3},{%4,%5,%6,%7},{%8,%9},{%0,%1,%2,%3};"
        : "+f"(c[0]), "+f"(c[1]), "+f"(c[2]), "+f"(c[3])
        : "r"(a0), "r"(a1), "r"(a2), "r"(a3), "r"(b0), "r"(b1));
}

__global__ void __launch_bounds__(256, 1)
k_conv(const float* __restrict__ lines,
       const float* __restrict__ bn1_g, const float* __restrict__ bn1_b,
       const float* __restrict__ conv1_w, const float* __restrict__ conv1_b,
       const float* __restrict__ bn2_g, const float* __restrict__ bn2_b,
       const float* __restrict__ conv2_w, const float* __restrict__ conv2_b,
       const float* __restrict__ bn3_g, const float* __restrict__ bn3_b,
       const float* __restrict__ conv3_w, const float* __restrict__ conv3_b,
       const float* __restrict__ fc2_w, const float* __restrict__ fc2_b,
       float* __restrict__ out)
{
    extern __shared__ char smem[];
    __half* hW1 = (__half*)(smem + OFF_W1);
    __half* hW2 = (__half*)(smem + OFF_W2);
    __half* hW3 = (__half*)(smem + OFF_W3);
    __half* hA  = (__half*)(smem + OFF_A);
    float*  sX  = (float*)(smem + OFF_SX);
    float*  sFC = (float*)(smem + OFF_FC);
    float*  sPar = (float*)(smem + OFF_PAR);
    float* s1  = sPar;        float* b1  = sPar + 128;
    float* c1b = sPar + 256;  float* s2  = sPar + 320;
    float* b2  = sPar + 384;  float* c2b = sPar + 448;
    float* s3  = sPar + 512;  float* b3  = sPar + 576;
    float* c3b = sPar + 640;

    int tid = threadIdx.x;
    int wid = tid >> 5, lane = tid & 31;
    int r = lane >> 2, cq = (lane & 3) * 2;
    int m0 = wid * 16;
    const float rs = rsqrtf(1.0f + 1e-5f);

    // ---- stage params + weights (f16) + fc2 + x ----
    for (int i = tid; i < 128; i += 256) {
        s1[i] = bn1_g[i] * rs; b1[i] = bn1_b[i]; c3b[i] = conv3_b[i];
    }
    for (int i = tid; i < 64; i += 256) {
        c1b[i] = conv1_b[i];
        s2[i] = bn2_g[i] * rs; b2[i] = bn2_b[i];
        c2b[i] = conv2_b[i];
        s3[i] = bn3_g[i] * rs; b3[i] = bn3_b[i];
    }
    for (int i = tid; i < 8192; i += 256) {        // W1 (64p,128c): hW1[p][c]
        int p = i >> 7, c = i & 127;
        hW1[p * W1S + c] = __float2half(conv1_w[i]);
    }
    for (int i = tid; i < 12288; i += 256) {       // W2 (64p,64q,3kk): hW2[p][kk*64+q]
        int p = i / 192, rm = i - p * 192, q = rm / 3, kk = rm - q * 3;
        hW2[p * W2S + kk * 64 + q] = __float2half(conv2_w[i]);
    }
    for (int i = tid; i < 8192; i += 256) {        // W3 (128c,64p): hW3[c][p]
        int c = i >> 6, p = i & 63;
        hW3[c * W3S + p] = __float2half(conv3_w[i]);
    }
    for (int i = tid; i < 4116; i += 256) sFC[i] = fc2_w[i];
    {
        const float4* src = (const float4*)(g_x + (size_t)blockIdx.x * 16 * 1024);
        for (int i = tid; i < 4096; i += 256) {
            int m = i >> 5, c4 = i & 31;
            *(float4*)&sX[m * SXS + c4 * 4] = src[i];
        }
    }
    __syncthreads();

    // ---- A1 = f16(relu(bn1(x))) : hA[m][c] ----
    for (int i = tid; i < 8192; i += 256) {
        int m = i >> 6, c2 = i & 63;
        float2 xx = *(const float2*)&sX[m * SXS + c2 * 2];
        float z0 = fmaxf(s1[c2*2]   * xx.x + b1[c2*2],   0.0f);
        float z1 = fmaxf(s1[c2*2+1] * xx.y + b1[c2*2+1], 0.0f);
        *(__half2*)&hA[m * AS + c2 * 2] = __floats2half2_rn(z0, z1);
    }
    __syncthreads();

    // ---- GEMM1: [128m x 64n] = A1[128,128] * W1^T, 8 ksteps ----
    float acc[8][4];
    #pragma unroll
    for (int nt = 0; nt < 8; nt++) { acc[nt][0]=0; acc[nt][1]=0; acc[nt][2]=0; acc[nt][3]=0; }
    #pragma unroll
    for (int ks = 0; ks < 8; ks++) {
        int k0 = ks * 16;
        int ab = (m0 + r) * AS + k0 + cq;
        uint32_t a0 = *(const uint32_t*)&hA[ab];
        uint32_t a1 = *(const uint32_t*)&hA[ab + 8*AS];
        uint32_t a2 = *(const uint32_t*)&hA[ab + 8];
        uint32_t a3 = *(const uint32_t*)&hA[ab + 8*AS + 8];
        #pragma unroll
        for (int nt = 0; nt < 8; nt++) {
            int bb = (nt*8 + r) * W1S + k0 + cq;
            uint32_t b0v = *(const uint32_t*)&hW1[bb];
            uint32_t b1v = *(const uint32_t*)&hW1[bb + 8];
            mma16816(acc[nt], a0, a1, a2, a3, b0v, b1v);
        }
    }
    __syncthreads();   // GEMM1 reads of hA done

    // ---- epilogue1: im2col scatter of relu(bn2(.)) into hA[(ln,t2)][kk*64+q] ----
    for (int i = tid; i < 1024; i += 256) {        // zero pad slots
        int ln = i >> 6, q = i & 63;
        hA[(ln*8)     * AS + q]        = __float2half(0.0f);
        hA[(ln*8 + 7) * AS + 128 + q]  = __float2half(0.0f);
    }
    #pragma unroll
    for (int nt = 0; nt < 8; nt++) {
        #pragma unroll
        for (int e = 0; e < 4; e++) {
            int n = nt*8 + cq + (e & 1);
            int m_e = m0 + r + ((e >> 1) ? 8 : 0);
            float z = fmaxf(s2[n] * (acc[nt][e] + c1b[n]) + b2[n], 0.0f);
            __half hz = __float2half(z);
            int ln = m_e >> 3, t = m_e & 7;
            #pragma unroll
            for (int kk = 0; kk < 3; kk++) {
                int t2 = t + 1 - kk;
                if (t2 >= 0 && t2 < 8) hA[(ln*8 + t2) * AS + kk*64 + n] = hz;
            }
        }
    }
    __syncthreads();

    // ---- GEMM2: K=192, 12 ksteps ----
    #pragma unroll
    for (int nt = 0; nt < 8; nt++) { acc[nt][0]=0; acc[nt][1]=0; acc[nt][2]=0; acc[nt][3]=0; }
    #pragma unroll
    for (int ks = 0; ks < 12; ks++) {
        int k0 = ks * 16;
        int ab = (m0 + r) * AS + k0 + cq;
        uint32_t a0 = *(const uint32_t*)&hA[ab];
        uint32_t a1 = *(const uint32_t*)&hA[ab + 8*AS];
        uint32_t a2 = *(const uint32_t*)&hA[ab + 8];
        uint32_t a3 = *(const uint32_t*)&hA[ab + 8*AS + 8];
        #pragma unroll
        for (int nt = 0; nt < 8; nt++) {
            int bb = (nt*8 + r) * W2S + k0 + cq;
            uint32_t b0v = *(const uint32_t*)&hW2[bb];
            uint32_t b1v = *(const uint32_t*)&hW2[bb + 8];
            mma16816(acc[nt], a0, a1, a2, a3, b0v, b1v);
        }
    }
    __syncthreads();

    // ---- epilogue2: A3[m][p] = f16(relu(bn3(.))) ----
    #pragma unroll
    for (int nt = 0; nt < 8; nt++) {
        #pragma unroll
        for (int e = 0; e < 4; e++) {
            int n = nt*8 + cq + (e & 1);
            int m_e = m0 + r + ((e >> 1) ? 8 : 0);
            float z = fmaxf(s3[n] * (acc[nt][e] + c2b[n]) + b3[n], 0.0f);
            hA[m_e * AS + n] = __float2half(z);
        }
    }
    __syncthreads();

    // ---- GEMM3 (K=64, N=128) fused with residual + FC partials ----
    uint32_t af[4][4];
    #pragma unroll
    for (int ks = 0; ks < 4; ks++) {
        int ab = (m0 + r) * AS + ks*16 + cq;
        af[ks][0] = *(const uint32_t*)&hA[ab];
        af[ks][1] = *(const uint32_t*)&hA[ab + 8*AS];
        af[ks][2] = *(const uint32_t*)&hA[ab + 8];
        af[ks][3] = *(const uint32_t*)&hA[ab + 8*AS + 8];
    }
    float pa0=0, pa1=0, pa2=0, pa3=0;   // line 2*wid   (rows m0..m0+7)
    float pb0=0, pb1=0, pb2=0, pb3=0;   // line 2*wid+1 (rows m0+8..m0+15)
    #pragma unroll
    for (int nt = 0; nt < 16; nt++) {
        float c4[4] = {0.f, 0.f, 0.f, 0.f};
        #pragma unroll
        for (int ks = 0; ks < 4; ks++) {
            int bb = (nt*8 + r) * W3S + ks*16 + cq;
            uint32_t b0v = *(const uint32_t*)&hW3[bb];
            uint32_t b1v = *(const uint32_t*)&hW3[bb + 8];
            mma16816(c4, af[ks][0], af[ks][1], af[ks][2], af[ks][3], b0v, b1v);
        }
        int n0e = nt*8 + cq;
        float2 x0 = *(const float2*)&sX[(m0 + r)     * SXS + n0e];
        float2 x1 = *(const float2*)&sX[(m0 + r + 8) * SXS + n0e];
        float cb0 = c3b[n0e], cb1 = c3b[n0e + 1];
        float v00 = fmaxf(x0.x + c4[0] + cb0, 0.0f);
        float v01 = fmaxf(x0.y + c4[1] + cb1, 0.0f);
        float v10 = fmaxf(x1.x + c4[2] + cb0, 0.0f);
        float v11 = fmaxf(x1.y + c4[3] + cb1, 0.0f);
        // FC index: k = c*8 + t, t = (m&7) = r for both rows
        int k0i = n0e * 8 + r, k1i = k0i + 8;
        float w00 = sFC[k0i],          w01 = sFC[k1i];
        float w10 = sFC[1029 + k0i],   w11 = sFC[1029 + k1i];
        float w20 = sFC[2058 + k0i],   w21 = sFC[2058 + k1i];
        float w30 = sFC[3087 + k0i],   w31 = sFC[3087 + k1i];
        pa0 += v00*w00 + v01*w01;  pb0 += v10*w00 + v11*w01;
        pa1 += v00*w10 + v01*w11;  pb1 += v10*w10 + v11*w11;
        pa2 += v00*w20 + v01*w21;  pb2 += v10*w20 + v11*w21;
        pa3 += v00*w30 + v01*w31;  pb3 += v10*w30 + v11*w31;
    }
    // ---- warp reductions + features + softmax ----
    #pragma unroll
    for (int off = 16; off; off >>= 1) {
        pa0 += __shfl_xor_sync(0xffffffffu, pa0, off);
        pa1 += __shfl_xor_sync(0xffffffffu, pa1, off);
        pa2 += __shfl_xor_sync(0xffffffffu, pa2, off);
        pa3 += __shfl_xor_sync(0xffffffffu, pa3, off);
        pb0 += __shfl_xor_sync(0xffffffffu, pb0, off);
        pb1 += __shfl_xor_sync(0xffffffffu, pb1, off);
        pb2 += __shfl_xor_sync(0xffffffffu, pb2, off);
        pb3 += __shfl_xor_sync(0xffffffffu, pb3, off);
    }
    if (lane < 2) {
        float q0 = lane ? pb0 : pa0;
        float q1 = lane ? pb1 : pa1;
        float q2 = lane ? pb2 : pa2;
        float q3 = lane ? pb3 : pa3;
        int gline = blockIdx.x * 16 + wid * 2 + lane;
        const float* lp = lines + (size_t)gline * 4;
        float f0 = fmaxf(lp[0] * (1.0f/128.0f), 0.0f);
        float f1 = fmaxf(lp[1] * (1.0f/128.0f), 0.0f);
        float f2 = fmaxf(lp[2] * (1.0f/128.0f), 0.0f);
        float f3 = fmaxf(lp[3] * (1.0f/128.0f), 0.0f);
        float dx = lp[0] - lp[2], dy = lp[1] - lp[3];
        float f4 = fmaxf(sqrtf(dx*dx + dy*dy), 1e-6f);
        q0 += f0*sFC[1024] + f1*sFC[1025] + f2*sFC[1026] + f3*sFC[1027] + f4*sFC[1028];
        q1 += f0*sFC[1029+1024] + f1*sFC[1029+1025] + f2*sFC[1029+1026] + f3*sFC[1029+1027] + f4*sFC[1029+1028];
        q2 += f0*sFC[2058+1024] + f1*sFC[2058+1025] + f2*sFC[2058+1026] + f3*sFC[2058+1027] + f4*sFC[2058+1028];
        q3 += f0*sFC[3087+1024] + f1*sFC[3087+1025] + f2*sFC[3087+1026] + f3*sFC[3087+1027] + f4*sFC[3087+1028];
        float l0 = q0 + fc2_b[0], l1 = q1 + fc2_b[1];
        float l2 = q2 + fc2_b[2], l3 = q3 + fc2_b[3];
        float mx = fmaxf(fmaxf(l0, l1), fmaxf(l2, l3));
        float e0 = expf(l0 - mx), e1 = expf(l1 - mx);
        float e2 = expf(l2 - mx), e3 = expf(l3 - mx);
        float inv = 1.0f / (e0 + e1 + e2 + e3);
        out[(size_t)gline * 4 + 0] = l0;
        out[(size_t)gline * 4 + 1] = l1;
        out[(size_t)gline * 4 + 2] = l2;
        out[(size_t)gline * 4 + 3] = l3;
        float* pr = out + (size_t)NLINES * 4;
        pr[(size_t)gline * 4 + 0] = e0 * inv;
        pr[(size_t)gline * 4 + 1] = e1 * inv;
        pr[(size_t)gline * 4 + 2] = e2 * inv;
        pr[(size_t)gline * 4 + 3] = e3 * inv;
    }
}

// ================= launcher =================
extern "C" void kernel_launch(void* const* d_in, const int* in_sizes, int n_in,
                              void* d_out, int out_size) {
    const float* fm      = (const float*)d_in[0];
    const float* lines   = (const float*)d_in[1];
    const float* bn1_g   = (const float*)d_in[2];
    const float* bn1_b   = (const float*)d_in[3];
    const float* conv1_w = (const float*)d_in[4];
    const float* conv1_b = (const float*)d_in[5];
    const float* bn2_g   = (const float*)d_in[6];
    const float* bn2_b   = (const float*)d_in[7];
    const float* conv2_w = (const float*)d_in[8];
    const float* conv2_b = (const float*)d_in[9];
    const float* bn3_g   = (const float*)d_in[10];
    const float* bn3_b   = (const float*)d_in[11];
    const float* conv3_w = (const float*)d_in[12];
    const float* conv3_b = (const float*)d_in[13];
    const float* fc2_w   = (const float*)d_in[14];
    const float* fc2_b   = (const float*)d_in[15];
    float* out = (float*)d_out;

    static int smem_set = 0;
    if (!smem_set) {
        cudaFuncSetAttribute(k_conv, cudaFuncAttributeMaxDynamicSharedMemorySize,
                             SMEM_BYTES);
        smem_set = 1;
    }

    k_transpose<<<dim3(WW / 32, CC / 32, BB * HH), dim3(32, 8)>>>(fm);
    k_gather<<<NLINES, 128>>>(lines);
    k_conv<<<NLINES / 16, 256, SMEM_BYTES>>>(
        lines, bn1_g, bn1_b, conv1_w, conv1_b, bn2_g, bn2_b,
        conv2_w, conv2_b, bn3_g, bn3_b, conv3_w, conv3_b,
        fc2_w, fc2_b, out);
}

// round 6
// speedup vs baseline: 4.0966x; 1.4173x over previous
#include <cuda_runtime.h>
#include <cuda_fp16.h>
#include <math.h>
#include <stdint.h>

#define BB 4
#define NLN 2048
#define CC 128
#define HH 128
#define WW 128
#define NPTS1 8
#define NLINES (BB*NLN)   // 8192

// -------- scratch (__device__ global: allocation-free) --------
__device__ __half g_fmt_h[(size_t)BB*HH*WW*CC];   // (B,H,W,C) f16, 16.8MB

// ================= kernel 1: transpose (B,C,H,W) fp32 -> (B,H,W,C) f16 ========
__global__ void k_transpose(const float* __restrict__ fm) {
    __shared__ float tile[32][33];                 // [c][w]
    int bh = blockIdx.z;
    int b = bh >> 7, h = bh & 127;
    int c0 = blockIdx.y * 32, w0 = blockIdx.x * 32;
    int tx = threadIdx.x, ty = threadIdx.y;
    #pragma unroll
    for (int i = 0; i < 32; i += 8) {
        int c = c0 + ty + i;
        tile[ty + i][tx] = fm[(((size_t)b*CC + c)*HH + h)*WW + w0 + tx];
    }
    __syncthreads();
    int tid = ty * 32 + tx;
    #pragma unroll
    for (int it = 0; it < 2; it++) {
        int s = it * 256 + tid;
        int wi = s >> 4, cp = s & 15;              // w row, c-pair
        __half2 v = __floats2half2_rn(tile[2*cp][wi], tile[2*cp+1][wi]);
        int w = w0 + wi, c = c0 + 2*cp;
        *(__half2*)&g_fmt_h[(((size_t)b*HH + h)*WW + w)*CC + c] = v;
    }
}

// ================= kernel 2: fused gather + conv stack + FC + softmax =========
// 16 lines/block (M=128 rows, m = ln*8+t1), 256 threads = 8 warps.
// Warp wid owns lines {2wid, 2wid+1}. Gather phase: lane = h*16+cl,
// h selects the line, cl selects an 8-channel f16 chunk (one uint4 per tap).
// GEMMs via mma.sync.m16n8k16 f16->f32, padded smem strides.
#define AS   200   // hA row stride (halves)
#define W1S  136
#define W2S  200
#define W3S  72
#define SXS  132   // sX row stride (floats)

#define OFF_W1   0
#define OFF_W2   (OFF_W1 + 64*W1S*2)
#define OFF_W3   (OFF_W2 + 64*W2S*2)
#define OFF_A    (OFF_W3 + 128*W3S*2)
#define OFF_SX   (OFF_A  + 128*AS*2)
#define OFF_FC   (OFF_SX + 128*SXS*4)
#define OFF_PAR  (OFF_FC + 4120*4)
#define SMEM_BYTES (OFF_PAR + 768*4)   // 199776

__device__ __forceinline__ void mma16816(float* c, uint32_t a0, uint32_t a1,
                                         uint32_t a2, uint32_t a3,
                                         uint32_t b0, uint32_t b1) {
    asm volatile(
        "mma.sync.aligned.m16n8k16.row.col.f32.f16.f16.f32 "
        "{%0,%1,%2,%3},{%4,%5,%6,%7},{%8,%9},{%0,%1,%2,%3};"
        : "+f"(c[0]), "+f"(c[1]), "+f"(c[2]), "+f"(c[3])
        : "r"(a0), "r"(a1), "r"(a2), "r"(a3), "r"(b0), "r"(b1));
}

__global__ void __launch_bounds__(256, 1)
k_main(const float* __restrict__ lines,
       const float* __restrict__ bn1_g, const float* __restrict__ bn1_b,
       const float* __restrict__ conv1_w, const float* __restrict__ conv1_b,
       const float* __restrict__ bn2_g, const float* __restrict__ bn2_b,
       const float* __restrict__ conv2_w, const float* __restrict__ conv2_b,
       const float* __restrict__ bn3_g, const float* __restrict__ bn3_b,
       const float* __restrict__ conv3_w, const float* __restrict__ conv3_b,
       const float* __restrict__ fc2_w, const float* __restrict__ fc2_b,
       float* __restrict__ out)
{
    extern __shared__ char smem[];
    __half* hW1 = (__half*)(smem + OFF_W1);
    __half* hW2 = (__half*)(smem + OFF_W2);
    __half* hW3 = (__half*)(smem + OFF_W3);
    __half* hA  = (__half*)(smem + OFF_A);
    float*  sX  = (float*)(smem + OFF_SX);
    float*  sFC = (float*)(smem + OFF_FC);
    float*  sPar = (float*)(smem + OFF_PAR);
    float* s1  = sPar;        float* b1  = sPar + 128;
    float* c1b = sPar + 256;  float* s2  = sPar + 320;
    float* b2  = sPar + 384;  float* c2b = sPar + 448;
    float* s3  = sPar + 512;  float* b3  = sPar + 576;
    float* c3b = sPar + 640;

    int tid = threadIdx.x;
    int wid = tid >> 5, lane = tid & 31;
    int r = lane >> 2, cq = (lane & 3) * 2;
    int m0 = wid * 16;
    const float rs = rsqrtf(1.0f + 1e-5f);

    // ---- stage params + weights (f16) + fc2 ----
    for (int i = tid; i < 128; i += 256) {
        s1[i] = bn1_g[i] * rs; b1[i] = bn1_b[i]; c3b[i] = conv3_b[i];
    }
    for (int i = tid; i < 64; i += 256) {
        c1b[i] = conv1_b[i];
        s2[i] = bn2_g[i] * rs; b2[i] = bn2_b[i];
        c2b[i] = conv2_b[i];
        s3[i] = bn3_g[i] * rs; b3[i] = bn3_b[i];
    }
    for (int i = tid; i < 8192; i += 256) {        // W1 (64p,128c): hW1[p][c]
        int p = i >> 7, c = i & 127;
        hW1[p * W1S + c] = __float2half(conv1_w[i]);
    }
    for (int i = tid; i < 12288; i += 256) {       // W2 (64p,64q,3kk): hW2[p][kk*64+q]
        int p = i / 192, rm = i - p * 192, q = rm / 3, kk = rm - q * 3;
        hW2[p * W2S + kk * 64 + q] = __float2half(conv2_w[i]);
    }
    for (int i = tid; i < 8192; i += 256) {        // W3 (128c,64p): hW3[c][p]
        int c = i >> 6, p = i & 63;
        hW3[c * W3S + p] = __float2half(conv3_w[i]);
    }
    for (int i = tid; i < 4116; i += 256) sFC[i] = fc2_w[i];
    __syncthreads();

    // ---- gather phase: LOI bilinear sample (f16 fm) + maxpool(4) ----
    // writes sX[m][c] (fp32 residual base) and hA[m][c] = f16(relu(bn1(x)))
    {
        int hsel = lane >> 4, cl = lane & 15;      // line-of-pair, 8ch chunk
        int lnl = wid * 2 + hsel;
        int gline = blockIdx.x * 16 + lnl;
        const float* lp = lines + (size_t)gline * 4;
        float e0x = lp[0], e0y = lp[1], e1x = lp[2], e1y = lp[3];
        int bidx = gline >> 11;
        const uint4* fmt = (const uint4*)(g_fmt_h + (size_t)bidx * HH * WW * CC);

        #pragma unroll
        for (int g = 0; g < 8; g++) {
            float mx[8];
            #pragma unroll
            for (int j = 0; j < 4; j++) {
                int t = g * 4 + j;
                float lam = (float)t * (1.0f / 31.0f);
                float px = e0x * lam + e1x * (1.0f - lam) - 0.5f;
                float py = e0y * lam + e1y * (1.0f - lam) - 0.5f;
                float fx0 = fminf(fmaxf(floorf(px), 0.0f), 127.0f);
                float fy0 = fminf(fmaxf(floorf(py), 0.0f), 127.0f);
                float fx1 = fminf(fx0 + 1.0f, 127.0f);
                float fy1 = fminf(fy0 + 1.0f, 127.0f);
                int x0 = (int)fx0, y0 = (int)fy0, x1 = (int)fx1, y1 = (int)fy1;
                float wa = (fx1 - px) * (fy1 - py);
                float wb = (px - fx0) * (fy1 - py);
                float wc = (fx1 - px) * (py - fy0);
                float wd = (px - fx0) * (py - fy0);
                uint4 u00 = fmt[(y0 * WW + x0) * 16 + cl];
                uint4 u10 = fmt[(y1 * WW + x0) * 16 + cl];
                uint4 u01 = fmt[(y0 * WW + x1) * 16 + cl];
                uint4 u11 = fmt[(y1 * WW + x1) * 16 + cl];
                const __half2* p00 = (const __half2*)&u00;
                const __half2* p10 = (const __half2*)&u10;
                const __half2* p01 = (const __half2*)&u01;
                const __half2* p11 = (const __half2*)&u11;
                #pragma unroll
                for (int q = 0; q < 4; q++) {
                    float2 v00 = __half22float2(p00[q]);
                    float2 v10 = __half22float2(p10[q]);
                    float2 v01 = __half22float2(p01[q]);
                    float2 v11 = __half22float2(p11[q]);
                    float sx0 = wa*v00.x + wb*v10.x + wc*v01.x + wd*v11.x;
                    float sx1 = wa*v00.y + wb*v10.y + wc*v01.y + wd*v11.y;
                    if (j == 0) { mx[2*q] = sx0; mx[2*q+1] = sx1; }
                    else { mx[2*q] = fmaxf(mx[2*q], sx0); mx[2*q+1] = fmaxf(mx[2*q+1], sx1); }
                }
            }
            int m = lnl * 8 + g;
            int c0 = cl * 8;
            *(float4*)&sX[m * SXS + c0]     = make_float4(mx[0], mx[1], mx[2], mx[3]);
            *(float4*)&sX[m * SXS + c0 + 4] = make_float4(mx[4], mx[5], mx[6], mx[7]);
            __half2 hz[4];
            #pragma unroll
            for (int q = 0; q < 4; q++) {
                int c = c0 + 2*q;
                float z0 = fmaxf(s1[c]   * mx[2*q]   + b1[c],   0.0f);
                float z1 = fmaxf(s1[c+1] * mx[2*q+1] + b1[c+1], 0.0f);
                hz[q] = __floats2half2_rn(z0, z1);
            }
            *(uint4*)&hA[m * AS + c0] = *(uint4*)hz;
        }
    }
    __syncthreads();

    // ---- GEMM1: [128m x 64n] = A1[128,128] * W1^T, 8 ksteps ----
    float acc[8][4];
    #pragma unroll
    for (int nt = 0; nt < 8; nt++) { acc[nt][0]=0; acc[nt][1]=0; acc[nt][2]=0; acc[nt][3]=0; }
    #pragma unroll
    for (int ks = 0; ks < 8; ks++) {
        int k0 = ks * 16;
        int ab = (m0 + r) * AS + k0 + cq;
        uint32_t a0 = *(const uint32_t*)&hA[ab];
        uint32_t a1 = *(const uint32_t*)&hA[ab + 8*AS];
        uint32_t a2 = *(const uint32_t*)&hA[ab + 8];
        uint32_t a3 = *(const uint32_t*)&hA[ab + 8*AS + 8];
        #pragma unroll
        for (int nt = 0; nt < 8; nt++) {
            int bb = (nt*8 + r) * W1S + k0 + cq;
            uint32_t b0v = *(const uint32_t*)&hW1[bb];
            uint32_t b1v = *(const uint32_t*)&hW1[bb + 8];
            mma16816(acc[nt], a0, a1, a2, a3, b0v, b1v);
        }
    }
    __syncthreads();

    // ---- epilogue1: im2col scatter of relu(bn2(.)) into hA[(ln,t2)][kk*64+q] ----
    for (int i = tid; i < 1024; i += 256) {
        int ln = i >> 6, q = i & 63;
        hA[(ln*8)     * AS + q]        = __float2half(0.0f);
        hA[(ln*8 + 7) * AS + 128 + q]  = __float2half(0.0f);
    }
    #pragma unroll
    for (int nt = 0; nt < 8; nt++) {
        #pragma unroll
        for (int e = 0; e < 4; e++) {
            int n = nt*8 + cq + (e & 1);
            int m_e = m0 + r + ((e >> 1) ? 8 : 0);
            float z = fmaxf(s2[n] * (acc[nt][e] + c1b[n]) + b2[n], 0.0f);
            __half hz = __float2half(z);
            int ln = m_e >> 3, t = m_e & 7;
            #pragma unroll
            for (int kk = 0; kk < 3; kk++) {
                int t2 = t + 1 - kk;
                if (t2 >= 0 && t2 < 8) hA[(ln*8 + t2) * AS + kk*64 + n] = hz;
            }
        }
    }
    __syncthreads();

    // ---- GEMM2: K=192, 12 ksteps ----
    #pragma unroll
    for (int nt = 0; nt < 8; nt++) { acc[nt][0]=0; acc[nt][1]=0; acc[nt][2]=0; acc[nt][3]=0; }
    #pragma unroll
    for (int ks = 0; ks < 12; ks++) {
        int k0 = ks * 16;
        int ab = (m0 + r) * AS + k0 + cq;
        uint32_t a0 = *(const uint32_t*)&hA[ab];
        uint32_t a1 = *(const uint32_t*)&hA[ab + 8*AS];
        uint32_t a2 = *(const uint32_t*)&hA[ab + 8];
        uint32_t a3 = *(const uint32_t*)&hA[ab + 8*AS + 8];
        #pragma unroll
        for (int nt = 0; nt < 8; nt++) {
            int bb = (nt*8 + r) * W2S + k0 + cq;
            uint32_t b0v = *(const uint32_t*)&hW2[bb];
            uint32_t b1v = *(const uint32_t*)&hW2[bb + 8];
            mma16816(acc[nt], a0, a1, a2, a3, b0v, b1v);
        }
    }
    __syncthreads();

    // ---- epilogue2: A3[m][p] = f16(relu(bn3(.))) ----
    #pragma unroll
    for (int nt = 0; nt < 8; nt++) {
        #pragma unroll
        for (int e = 0; e < 4; e++) {
            int n = nt*8 + cq + (e & 1);
            int m_e = m0 + r + ((e >> 1) ? 8 : 0);
            float z = fmaxf(s3[n] * (acc[nt][e] + c2b[n]) + b3[n], 0.0f);
            hA[m_e * AS + n] = __float2half(z);
        }
    }
    __syncthreads();

    // ---- GEMM3 (K=64, N=128) fused with residual + FC partials ----
    uint32_t af[4][4];
    #pragma unroll
    for (int ks = 0; ks < 4; ks++) {
        int ab = (m0 + r) * AS + ks*16 + cq;
        af[ks][0] = *(const uint32_t*)&hA[ab];
        af[ks][1] = *(const uint32_t*)&hA[ab + 8*AS];
        af[ks][2] = *(const uint32_t*)&hA[ab + 8];
        af[ks][3] = *(const uint32_t*)&hA[ab + 8*AS + 8];
    }
    float pa0=0, pa1=0, pa2=0, pa3=0;
    float pb0=0, pb1=0, pb2=0, pb3=0;
    #pragma unroll
    for (int nt = 0; nt < 16; nt++) {
        float c4[4] = {0.f, 0.f, 0.f, 0.f};
        #pragma unroll
        for (int ks = 0; ks < 4; ks++) {
            int bb = (nt*8 + r) * W3S + ks*16 + cq;
            uint32_t b0v = *(const uint32_t*)&hW3[bb];
            uint32_t b1v = *(const uint32_t*)&hW3[bb + 8];
            mma16816(c4, af[ks][0], af[ks][1], af[ks][2], af[ks][3], b0v, b1v);
        }
        int n0e = nt*8 + cq;
        float2 x0 = *(const float2*)&sX[(m0 + r)     * SXS + n0e];
        float2 x1 = *(const float2*)&sX[(m0 + r + 8) * SXS + n0e];
        float cb0 = c3b[n0e], cb1 = c3b[n0e + 1];
        float v00 = fmaxf(x0.x + c4[0] + cb0, 0.0f);
        float v01 = fmaxf(x0.y + c4[1] + cb1, 0.0f);
        float v10 = fmaxf(x1.x + c4[2] + cb0, 0.0f);
        float v11 = fmaxf(x1.y + c4[3] + cb1, 0.0f);
        int k0i = n0e * 8 + r, k1i = k0i + 8;
        float w00 = sFC[k0i],          w01 = sFC[k1i];
        float w10 = sFC[1029 + k0i],   w11 = sFC[1029 + k1i];
        float w20 = sFC[2058 + k0i],   w21 = sFC[2058 + k1i];
        float w30 = sFC[3087 + k0i],   w31 = sFC[3087 + k1i];
        pa0 += v00*w00 + v01*w01;  pb0 += v10*w00 + v11*w01;
        pa1 += v00*w10 + v01*w11;  pb1 += v10*w10 + v11*w11;
        pa2 += v00*w20 + v01*w21;  pb2 += v10*w20 + v11*w21;
        pa3 += v00*w30 + v01*w31;  pb3 += v10*w30 + v11*w31;
    }
    #pragma unroll
    for (int off = 16; off; off >>= 1) {
        pa0 += __shfl_xor_sync(0xffffffffu, pa0, off);
        pa1 += __shfl_xor_sync(0xffffffffu, pa1, off);
        pa2 += __shfl_xor_sync(0xffffffffu, pa2, off);
        pa3 += __shfl_xor_sync(0xffffffffu, pa3, off);
        pb0 += __shfl_xor_sync(0xffffffffu, pb0, off);
        pb1 += __shfl_xor_sync(0xffffffffu, pb1, off);
        pb2 += __shfl_xor_sync(0xffffffffu, pb2, off);
        pb3 += __shfl_xor_sync(0xffffffffu, pb3, off);
    }
    if (lane < 2) {
        float q0 = lane ? pb0 : pa0;
        float q1 = lane ? pb1 : pa1;
        float q2 = lane ? pb2 : pa2;
        float q3 = lane ? pb3 : pa3;
        int gline = blockIdx.x * 16 + wid * 2 + lane;
        const float* lp = lines + (size_t)gline * 4;
        float f0 = fmaxf(lp[0] * (1.0f/128.0f), 0.0f);
        float f1 = fmaxf(lp[1] * (1.0f/128.0f), 0.0f);
        float f2 = fmaxf(lp[2] * (1.0f/128.0f), 0.0f);
        float f3 = fmaxf(lp[3] * (1.0f/128.0f), 0.0f);
        float dx = lp[0] - lp[2], dy = lp[1] - lp[3];
        float f4 = fmaxf(sqrtf(dx*dx + dy*dy), 1e-6f);
        q0 += f0*sFC[1024] + f1*sFC[1025] + f2*sFC[1026] + f3*sFC[1027] + f4*sFC[1028];
        q1 += f0*sFC[1029+1024] + f1*sFC[1029+1025] + f2*sFC[1029+1026] + f3*sFC[1029+1027] + f4*sFC[1029+1028];
        q2 += f0*sFC[2058+1024] + f1*sFC[2058+1025] + f2*sFC[2058+1026] + f3*sFC[2058+1027] + f4*sFC[2058+1028];
        q3 += f0*sFC[3087+1024] + f1*sFC[3087+1025] + f2*sFC[3087+1026] + f3*sFC[3087+1027] + f4*sFC[3087+1028];
        float l0 = q0 + fc2_b[0], l1 = q1 + fc2_b[1];
        float l2 = q2 + fc2_b[2], l3 = q3 + fc2_b[3];
        float mx = fmaxf(fmaxf(l0, l1), fmaxf(l2, l3));
        float e0 = expf(l0 - mx), e1 = expf(l1 - mx);
        float e2 = expf(l2 - mx), e3 = expf(l3 - mx);
        float inv = 1.0f / (e0 + e1 + e2 + e3);
        out[(size_t)gline * 4 + 0] = l0;
        out[(size_t)gline * 4 + 1] = l1;
        out[(size_t)gline * 4 + 2] = l2;
        out[(size_t)gline * 4 + 3] = l3;
        float* pr = out + (size_t)NLINES * 4;
        pr[(size_t)gline * 4 + 0] = e0 * inv;
        pr[(size_t)gline * 4 + 1] = e1 * inv;
        pr[(size_t)gline * 4 + 2] = e2 * inv;
        pr[(size_t)gline * 4 + 3] = e3 * inv;
    }
}

// ================= launcher =================
extern "C" void kernel_launch(void* const* d_in, const int* in_sizes, int n_in,
                              void* d_out, int out_size) {
    const float* fm      = (const float*)d_in[0];
    const float* lines   = (const float*)d_in[1];
    const float* bn1_g   = (const float*)d_in[2];
    const float* bn1_b   = (const float*)d_in[3];
    const float* conv1_w = (const float*)d_in[4];
    const float* conv1_b = (const float*)d_in[5];
    const float* bn2_g   = (const float*)d_in[6];
    const float* bn2_b   = (const float*)d_in[7];
    const float* conv2_w = (const float*)d_in[8];
    const float* conv2_b = (const float*)d_in[9];
    const float* bn3_g   = (const float*)d_in[10];
    const float* bn3_b   = (const float*)d_in[11];
    const float* conv3_w = (const float*)d_in[12];
    const float* conv3_b = (const float*)d_in[13];
    const float* fc2_w   = (const float*)d_in[14];
    const float* fc2_b   = (const float*)d_in[15];
    float* out = (float*)d_out;

    static int smem_set = 0;
    if (!smem_set) {
        cudaFuncSetAttribute(k_main, cudaFuncAttributeMaxDynamicSharedMemorySize,
                             SMEM_BYTES);
        smem_set = 1;
    }

    k_transpose<<<dim3(WW / 32, CC / 32, BB * HH), dim3(32, 8)>>>(fm);
    k_main<<<NLINES / 16, 256, SMEM_BYTES>>>(
        lines, bn1_g, bn1_b, conv1_w, conv1_b, bn2_g, bn2_b,
        conv2_w, conv2_b, bn3_g, bn3_b, conv3_w, conv3_b,
        fc2_w, fc2_b, out);
}